// round 2
// baseline (speedup 1.0000x reference)
#include <cuda_runtime.h>
#include <cstdint>

// Problem shape (static per reference): N=2048, L=512, D=256, B=256
#define N_PROT 2048
#define L_SEQ  512
#define D_DIM  256
#define B_SEG  256

// Scratch: __device__ globals (no allocation allowed)
__device__ float g_acc[B_SEG * D_DIM];   // segment sums
__device__ int   g_cnt[B_SEG];           // token counts per segment

__global__ void zero_kernel() {
    int i = blockIdx.x * blockDim.x + threadIdx.x;   // 65536 threads
    if (i < B_SEG * D_DIM) g_acc[i] = 0.0f;
    if (i < B_SEG)         g_cnt[i] = 0;
}

// Dtype-robust key fetch. keys buffer is either int32[2048] or int64[2048].
// Sorted keys in [0,256) with every segment non-empty => last key == 255.
//   int32 layout: word[2047] == 255
//   int64 layout: word[2047] == high word of element 1023 == 0
__device__ __forceinline__ int load_key(const int* k32, int n) {
    const bool is32 = (__ldg(&k32[N_PROT - 1]) == (B_SEG - 1));
    int key;
    if (is32) {
        key = __ldg(&k32[n]);
    } else {
        key = __ldg(&k32[2 * n]);   // little-endian low word of int64
    }
    // clamp: never let a bad key form a wild address
    return min(max(key, 0), B_SEG - 1);
}

// One CTA per protein. 256 threads: thread t handles float4-column (t&63)
// for rows l = (t>>6), (t>>6)+4, ... (128 rows each). Each warp reads 512B
// contiguous per iteration — fully coalesced streaming.
__global__ __launch_bounds__(256) void pool_kernel(
    const float* __restrict__ embeds,   // [N, L, D] fp32
    const int* __restrict__ keys_raw    // int32 view of batch_keys
) {
    const int n = blockIdx.x;
    const int t = threadIdx.x;
    const int key = load_key(keys_raw, n);

    const float4* __restrict__ row =
        (const float4*)(embeds + (size_t)n * (L_SEQ * D_DIM));
    const int c  = t & 63;   // float4 column index (0..63)
    const int r0 = t >> 6;   // row-phase (0..3)

    float4 acc = make_float4(0.f, 0.f, 0.f, 0.f);
    #pragma unroll 8
    for (int l = r0; l < L_SEQ; l += 4) {
        float4 v = __ldg(&row[l * (D_DIM / 4) + c]);
        acc.x += v.x; acc.y += v.y; acc.z += v.z; acc.w += v.w;
    }

    __shared__ float4 sdata[256];
    sdata[t] = acc;
    __syncthreads();

    if (t < 64) {
        float4 a = sdata[t];
        float4 b = sdata[t + 64];
        float4 e = sdata[t + 128];
        float4 f = sdata[t + 192];
        float4 r = make_float4(a.x + b.x + e.x + f.x,
                               a.y + b.y + e.y + f.y,
                               a.z + b.z + e.z + f.z,
                               a.w + b.w + e.w + f.w);
        float* dst = g_acc + key * D_DIM + t * 4;
        atomicAdd(dst + 0, r.x);
        atomicAdd(dst + 1, r.y);
        atomicAdd(dst + 2, r.z);
        atomicAdd(dst + 3, r.w);
    }
    if (t == 0) atomicAdd(&g_cnt[key], L_SEQ);
}

__global__ void finalize_kernel(float* __restrict__ out) {
    int i = blockIdx.x * blockDim.x + threadIdx.x;   // 65536
    int b = i >> 8;                                   // i / D_DIM
    out[i] = g_acc[i] / (float)g_cnt[b];
}

extern "C" void kernel_launch(void* const* d_in, const int* in_sizes, int n_in,
                              void* d_out, int out_size) {
    const float* embeds = (const float*)d_in[0];
    const int*   keys   = (const int*)d_in[1];   // int32 view; dtype detected in-kernel
    float*       out    = (float*)d_out;

    zero_kernel<<<256, 256>>>();
    pool_kernel<<<N_PROT, 256>>>(embeds, keys);
    finalize_kernel<<<256, 256>>>(out);
}

// round 3
// speedup vs baseline: 1.0039x; 1.0039x over previous
#include <cuda_runtime.h>
#include <cstdint>

// Problem shape (static per reference): N=2048, L=512, D=256, B=256
#define N_PROT 2048
#define L_SEQ  512
#define D_DIM  256
#define B_SEG  256

// Scratch (__device__ globals are zero-initialized at module load; the
// finalizer restores them to zero each launch, keeping the invariant
// across graph replays).
__device__ float g_acc[B_SEG * D_DIM];   // segment sums
__device__ int   g_done[B_SEG];          // CTAs-arrived counter per segment

// Dtype-robust key fetch. keys buffer is either int32[2048] or int64[2048].
// Sorted keys in [0,256) with every segment non-empty => last key == 255.
//   int32 layout: word[2047] == 255
//   int64 layout: word[2047] == high word of element 1023 == 0
__device__ __forceinline__ int load_key(const int* k32, bool is32, int n) {
    int key = is32 ? __ldg(&k32[n]) : __ldg(&k32[2 * n]);
    return min(max(key, 0), B_SEG - 1);   // never form a wild address
}

// One CTA per protein. 256 threads: thread t streams float4-column (t&63)
// over rows l = (t>>6), (t>>6)+4, ...  Warp reads 512B contiguous / iter.
// Last CTA of each (sorted) segment finalizes: spin until all peers'
// atomics have landed, divide, write out, reset scratch to zero.
__global__ __launch_bounds__(256) void pool_fused_kernel(
    const float* __restrict__ embeds,    // [N, L, D] fp32
    const int* __restrict__ keys_raw,    // int32 view of batch_keys
    float* __restrict__ out              // [B, D] fp32
) {
    const int n = blockIdx.x;
    const int t = threadIdx.x;
    const bool is32 = (__ldg(&keys_raw[N_PROT - 1]) == (B_SEG - 1));
    const int key = load_key(keys_raw, is32, n);
    const bool is_last =
        (n == N_PROT - 1) || (load_key(keys_raw, is32, n + 1) != key);

    // ---- streaming partial sum (HBM-bound, at roofline) ----
    const float4* __restrict__ row =
        (const float4*)(embeds + (size_t)n * (L_SEQ * D_DIM));
    const int c  = t & 63;   // float4 column (0..63)
    const int r0 = t >> 6;   // row-phase (0..3)

    float4 acc = make_float4(0.f, 0.f, 0.f, 0.f);
    #pragma unroll 8
    for (int l = r0; l < L_SEQ; l += 4) {
        float4 v = __ldg(&row[l * (D_DIM / 4) + c]);
        acc.x += v.x; acc.y += v.y; acc.z += v.z; acc.w += v.w;
    }

    __shared__ float4 sdata[256];
    sdata[t] = acc;
    __syncthreads();

    if (t < 64) {
        float4 a = sdata[t];
        float4 b = sdata[t + 64];
        float4 e = sdata[t + 128];
        float4 f = sdata[t + 192];
        float* dst = g_acc + key * D_DIM + t * 4;
        atomicAdd(dst + 0, a.x + b.x + e.x + f.x);
        atomicAdd(dst + 1, a.y + b.y + e.y + f.y);
        atomicAdd(dst + 2, a.z + b.z + e.z + f.z);
        atomicAdd(dst + 3, a.w + b.w + e.w + f.w);
        __threadfence();   // release: my g_acc atomics visible before signal
    }
    __syncthreads();

    if (t == 0) atomicAdd(&g_done[key], 1);

    if (!is_last) return;

    // ---- finalizer (exactly one CTA per segment) ----
    __shared__ int s_count;
    if (t == 0) {
        // first index of this segment in the sorted keys
        int lo = 0, hi = n;
        while (lo < hi) {
            int mid = (lo + hi) >> 1;
            if (load_key(keys_raw, is32, mid) < key) lo = mid + 1;
            else hi = mid;
        }
        const int count = n - lo + 1;      // proteins in this segment
        // acquire: wait for all peers' signals
        while (atomicAdd(&g_done[key], 0) < count) __nanosleep(64);
        __threadfence();
        g_done[key] = 0;                   // reset for next replay
        s_count = count;
    }
    __syncthreads();

    const float inv = 1.0f / ((float)s_count * (float)L_SEQ);
    const int i = key * D_DIM + t;         // one column per thread
    const float sum = atomicAdd(&g_acc[i], 0.0f);   // L2-coherent read
    out[i] = sum * inv;
    g_acc[i] = 0.0f;                       // reset for next replay
}

extern "C" void kernel_launch(void* const* d_in, const int* in_sizes, int n_in,
                              void* d_out, int out_size) {
    const float* embeds = (const float*)d_in[0];
    const int*   keys   = (const int*)d_in[1];   // int32 view; dtype detected in-kernel
    float*       out    = (float*)d_out;

    pool_fused_kernel<<<N_PROT, 256>>>(embeds, keys, out);
}